// round 14
// baseline (speedup 1.0000x reference)
#include <cuda_runtime.h>
#include <cuda_fp16.h>
#include <cstdint>
#include <math.h>

// RingAttention out = softmax(Q K^T) V, B=32, SQ=1024, SKV=8192, D=64, fp32.
// R14: R13 + NCHUNK=8 (wave quantization 86%->99%) + pre-split Q to gmem
//      (attn prologue = cp.async only; smem down to 64KB).

#define B_   32
#define SQ_  1024
#define SKV_ 8192
#define D_   64
#define TQ   128
#define TKV  64
#define NT   (SKV_ / TKV)      // 128
#define NCHUNK 8
#define CT   (NT / NCHUNK)     // 16 tiles per chunk
#define NQB  (SQ_ / TQ)        // 8
#define NITEM (B_ * NQB)       // 256

#define BLK_BYTES 24576
__device__ uint8_t gKV[(size_t)B_ * NT * BLK_BYTES];            // 96 MB
__device__ uint8_t gQ[(size_t)NITEM * 32768];                   // 8 MB (QH|QL images)
__device__ float   gOP[(size_t)NITEM * NCHUNK * TQ * D_];       // 64 MB partials
__device__ float2  gML[(size_t)NITEM * NCHUNK * TQ];            // 2 MB (m, l)

// attn smem (64KB): QL 0..16K persistent; stage0 16K..40K; stage1 40K..64K.
// QH image staged transiently in stage0 during the prologue.
#define QL_OFF 0
#define STG0   16384
#define KH_OFF 0
#define KL_OFF 8192
#define VH_OFF 16384
#define SMEM_BYTES (16384 + 2 * BLK_BYTES)   // 65536

__device__ __forceinline__ uint32_t smem_u32(const void* p) {
    uint32_t a;
    asm("{ .reg .u64 t; cvta.to.shared.u64 t, %1; cvt.u32.u64 %0, t; }" : "=r"(a) : "l"(p));
    return a;
}
__device__ __forceinline__ void ldsm4(uint32_t r[4], uint32_t a) {
    asm volatile("ldmatrix.sync.aligned.m8n8.x4.shared.b16 {%0,%1,%2,%3}, [%4];"
                 : "=r"(r[0]), "=r"(r[1]), "=r"(r[2]), "=r"(r[3]) : "r"(a));
}
__device__ __forceinline__ void ldsm4t(uint32_t r[4], uint32_t a) {
    asm volatile("ldmatrix.sync.aligned.m8n8.x4.trans.shared.b16 {%0,%1,%2,%3}, [%4];"
                 : "=r"(r[0]), "=r"(r[1]), "=r"(r[2]), "=r"(r[3]) : "r"(a));
}
__device__ __forceinline__ void mma16816h(float* c, const uint32_t* a, uint32_t b0, uint32_t b1) {
    asm volatile("mma.sync.aligned.m16n8k16.row.col.f32.f16.f16.f32 "
                 "{%0,%1,%2,%3}, {%4,%5,%6,%7}, {%8,%9}, {%0,%1,%2,%3};"
                 : "+f"(c[0]), "+f"(c[1]), "+f"(c[2]), "+f"(c[3])
                 : "r"(a[0]), "r"(a[1]), "r"(a[2]), "r"(a[3]), "r"(b0), "r"(b1));
}
__device__ __forceinline__ float ex2f(float x) {
    float r;
    asm("ex2.approx.f32 %0, %1;" : "=f"(r) : "f"(x));
    return r;
}
__device__ __forceinline__ uint32_t exp2pairh(float x, float y) {
    uint32_t d, r;
    asm("cvt.rn.f16x2.f32 %0, %1, %2;" : "=r"(d) : "f"(y), "f"(x));
    asm("ex2.approx.f16x2 %0, %1;" : "=r"(r) : "r"(d));
    return r;
}
__device__ __forceinline__ uint32_t packh(float x, float y) {
    __half2 h = __floats2half2_rn(x, y);
    return *reinterpret_cast<uint32_t*>(&h);
}
__device__ __forceinline__ void split2h(float x, float y, uint32_t& h, uint32_t& l) {
    __half2 hp = __floats2half2_rn(x, y);
    float rx = x - __half2float(__low2half(hp));
    float ry = y - __half2float(__high2half(hp));
    __half2 lp = __floats2half2_rn(rx, ry);
    h = *reinterpret_cast<uint32_t*>(&hp);
    l = *reinterpret_cast<uint32_t*>(&lp);
}
__device__ __forceinline__ void cvt8h(float4 a, float4 b, uint4& h, uint4& l) {
    split2h(a.x, a.y, h.x, l.x);
    split2h(a.z, a.w, h.y, l.y);
    split2h(b.x, b.y, h.z, l.z);
    split2h(b.z, b.w, h.w, l.w);
}
__device__ __forceinline__ uint4 cvt8h1(float4 a, float4 b) {
    uint4 h;
    h.x = packh(a.x, a.y);
    h.y = packh(a.z, a.w);
    h.z = packh(b.x, b.y);
    h.w = packh(b.z, b.w);
    return h;
}
__device__ __forceinline__ float2 hsum8(const uint32_t* p, int stride) {
    __half2 a0 = __hadd2(*(const __half2*)&p[0 * stride], *(const __half2*)&p[1 * stride]);
    __half2 a1 = __hadd2(*(const __half2*)&p[2 * stride], *(const __half2*)&p[3 * stride]);
    __half2 a2 = __hadd2(*(const __half2*)&p[4 * stride], *(const __half2*)&p[5 * stride]);
    __half2 a3 = __hadd2(*(const __half2*)&p[6 * stride], *(const __half2*)&p[7 * stride]);
    __half2 s = __hadd2(__hadd2(a0, a1), __hadd2(a2, a3));
    return __half22float2(s);
}
#define CP_ASYNC16(dst, src) \
    asm volatile("cp.async.cg.shared.global [%0], [%1], 16;" :: "r"(dst), "l"(src))
#define CP_COMMIT() asm volatile("cp.async.commit_group;" ::: "memory")
#define CP_WAIT0()  asm volatile("cp.async.wait_group 0;" ::: "memory")

// ===================== kernel A1: split K/V ======================
__global__ __launch_bounds__(256)
void split_kv_kernel(const float* __restrict__ K, const float* __restrict__ V)
{
    const int t = blockIdx.x;
    const int b = blockIdx.y;
    const int tid = threadIdx.x;

    const float* Kt = K + ((size_t)b * SKV_ + (size_t)t * TKV) * D_;
    const float* Vt = V + ((size_t)b * SKV_ + (size_t)t * TKV) * D_;
    uint8_t* blk = gKV + ((size_t)b * NT + t) * BLK_BYTES;

    #pragma unroll
    for (int uu = 0; uu < 2; ++uu) {
        const int u = tid + 256 * uu;
        const int r = u >> 3;
        const int c = u & 7;
        const uint32_t off = (uint32_t)r * 128 + (uint32_t)((c ^ (r & 7)) * 16);
        const float4* kp = (const float4*)(Kt + (size_t)r * D_ + c * 8);
        const float4* vp = (const float4*)(Vt + (size_t)r * D_ + c * 8);
        uint4 h, l;
        cvt8h(kp[0], kp[1], h, l);
        *(uint4*)(blk + KH_OFF + off) = h;
        *(uint4*)(blk + KL_OFF + off) = l;
        *(uint4*)(blk + VH_OFF + off) = cvt8h1(vp[0], vp[1]);
    }
}

// ===================== kernel A2: split Q (pre-scaled by log2 e) ======================
__global__ __launch_bounds__(128)
void split_q_kernel(const float* __restrict__ Q)
{
    const int qblk = blockIdx.x;
    const int b    = blockIdx.y;
    const int r    = threadIdx.x;    // one 64-float row per thread

    const float4* qp = (const float4*)(Q + ((size_t)b * SQ_ + qblk * TQ + r) * D_);
    uint8_t* dst = gQ + (size_t)(b * NQB + qblk) * 32768;
    const float LG2E = 1.4426950408889634f;

    #pragma unroll
    for (int c = 0; c < 8; ++c) {
        float4 f0 = qp[2 * c], f1 = qp[2 * c + 1];
        f0.x *= LG2E; f0.y *= LG2E; f0.z *= LG2E; f0.w *= LG2E;
        f1.x *= LG2E; f1.y *= LG2E; f1.z *= LG2E; f1.w *= LG2E;
        uint4 h, l;
        cvt8h(f0, f1, h, l);
        uint32_t x = (uint32_t)r * 128 + (uint32_t)((c ^ (r & 7)) * 16);
        *(uint4*)(dst + x)         = h;    // QH image
        *(uint4*)(dst + 16384 + x) = l;    // QL image
    }
}

// ===================== kernel B: attention partial ======================
__global__ __launch_bounds__(128, 2)
void attn_part_kernel()
{
    extern __shared__ char sm[];
    const uint32_t smb = smem_u32(sm);
    const int tid  = threadIdx.x;
    const int wid  = tid >> 5;
    const int lane = tid & 31;
    const uint32_t l7  = lane & 7;
    const uint32_t l8  = (lane >> 3) & 1;
    const uint32_t l15 = lane & 15;
    const uint32_t l16 = (uint32_t)lane >> 4;
    const int qblk  = blockIdx.x;
    const int b     = blockIdx.y;
    const int chunk = blockIdx.z;
    const int t0 = chunk * CT;

    const uint8_t* blk0 = gKV + (size_t)b * NT * BLK_BYTES;
    const uint8_t* qsrc = gQ + (size_t)(b * NQB + qblk) * 32768;

    // ---- prologue: cp.async QH image -> stage0 (transient), QL image -> QL region ----
    {
        const uint32_t dstH = smb + STG0 + (uint32_t)tid * 16;
        const uint32_t dstL = smb + QL_OFF + (uint32_t)tid * 16;
        #pragma unroll
        for (int i = 0; i < 8; ++i) {
            CP_ASYNC16(dstH + i * 2048, qsrc + (size_t)tid * 16 + i * 2048);
            CP_ASYNC16(dstL + i * 2048, qsrc + 16384 + (size_t)tid * 16 + i * 2048);
        }
        CP_COMMIT();
        CP_WAIT0();
    }
    __syncthreads();

    // hoist Qh fragments from stage0 (QL stays resident at QL_OFF)
    uint32_t qhr[2][4][4];
    #pragma unroll
    for (int mb = 0; mb < 2; ++mb)
        #pragma unroll
        for (int ks = 0; ks < 4; ++ks) {
            uint32_t a = smb + STG0
                       + (uint32_t)(wid * 32 + mb * 16 + (int)l15) * 128
                       + (((2u * ks + l16) ^ l7) * 16);
            ldsm4(qhr[mb][ks], a);
        }
    __syncthreads();   // all warps done reading QH before tile 0 overwrites stage0

    {
        const uint32_t dst = smb + STG0 + (uint32_t)tid * 16;
        const uint8_t* src = blk0 + (size_t)t0 * BLK_BYTES + (size_t)tid * 16;
        #pragma unroll
        for (int i = 0; i < 12; ++i)
            CP_ASYNC16(dst + i * 2048, src + i * 2048);
        CP_COMMIT();
    }

    const uint32_t krowb = (8 * l16 + l7) * 128;
    const uint32_t vrowb = l15 * 128;
    const uint32_t qlrow = (uint32_t)(wid * 32 + (int)l15) * 128;

    float o[2][8][4];
    float ls[2][2];
    #pragma unroll
    for (int mb = 0; mb < 2; ++mb) {
        #pragma unroll
        for (int nb = 0; nb < 8; ++nb)
            #pragma unroll
            for (int c = 0; c < 4; ++c) o[mb][nb][c] = 0.f;
        ls[mb][0] = 0.f; ls[mb][1] = 0.f;
    }
    float m[2][2] = {{-1e30f, -1e30f}, {-1e30f, -1e30f}};

    for (int lt = 0; lt < CT; ++lt) {
        const int t = t0 + lt;
        CP_WAIT0();
        __syncthreads();

        if (lt + 1 < CT) {
            const uint32_t dst = smb + STG0 + (uint32_t)(((lt + 1) & 1) * BLK_BYTES)
                                 + (uint32_t)tid * 16;
            const uint8_t* src = blk0 + (size_t)(t + 1) * BLK_BYTES + (size_t)tid * 16;
            #pragma unroll
            for (int i = 0; i < 12; ++i)
                CP_ASYNC16(dst + i * 2048, src + i * 2048);
            CP_COMMIT();
        }

        const uint32_t sbase = smb + STG0 + (uint32_t)((lt & 1) * BLK_BYTES);

        // ======== phase 1: S(mb0) full + S(mb1) ks0-1 ========
        float s0[8][4], s1[8][4];
        #pragma unroll
        for (int nb = 0; nb < 8; ++nb)
            #pragma unroll
            for (int c = 0; c < 4; ++c) { s0[nb][c] = 0.f; s1[nb][c] = 0.f; }

        #pragma unroll
        for (int ks = 0; ks < 4; ++ks) {
            const uint32_t qx = ((2u * ks + l16) ^ l7) * 16;
            const uint32_t kx = ((2u * ks + l8) ^ l7) * 16;
            uint32_t ql0[4], ql1[4];
            ldsm4(ql0, smb + QL_OFF + qlrow + qx);
            if (ks < 2) ldsm4(ql1, smb + QL_OFF + qlrow + 2048 + qx);
            #pragma unroll
            for (int jp = 0; jp < 4; ++jp) {
                uint32_t kh4[4], kl4[4];
                ldsm4(kh4, sbase + KH_OFF + krowb + (uint32_t)jp * 2048 + kx);
                ldsm4(kl4, sbase + KL_OFF + krowb + (uint32_t)jp * 2048 + kx);
                mma16816h(s0[2 * jp],     qhr[0][ks], kh4[0], kh4[1]);
                mma16816h(s0[2 * jp + 1], qhr[0][ks], kh4[2], kh4[3]);
                mma16816h(s0[2 * jp],     ql0, kh4[0], kh4[1]);
                mma16816h(s0[2 * jp + 1], ql0, kh4[2], kh4[3]);
                mma16816h(s0[2 * jp],     qhr[0][ks], kl4[0], kl4[1]);
                mma16816h(s0[2 * jp + 1], qhr[0][ks], kl4[2], kl4[3]);
                if (ks < 2) {
                    mma16816h(s1[2 * jp],     qhr[1][ks], kh4[0], kh4[1]);
                    mma16816h(s1[2 * jp + 1], qhr[1][ks], kh4[2], kh4[3]);
                    mma16816h(s1[2 * jp],     ql1, kh4[0], kh4[1]);
                    mma16816h(s1[2 * jp + 1], ql1, kh4[2], kh4[3]);
                    mma16816h(s1[2 * jp],     qhr[1][ks], kl4[0], kl4[1]);
                    mma16816h(s1[2 * jp + 1], qhr[1][ks], kl4[2], kl4[3]);
                }
            }
        }

        // ======== phase 2: mb0 max/shfl first, S(mb1) ks2-3 fills latency ========
        float m00t = s0[0][0], m01t = s0[0][2];
        #pragma unroll
        for (int nb = 0; nb < 8; ++nb) {
            m00t = fmaxf(m00t, fmaxf(s0[nb][0], s0[nb][1]));
            m01t = fmaxf(m01t, fmaxf(s0[nb][2], s0[nb][3]));
        }
        m00t = fmaxf(m00t, __shfl_xor_sync(0xffffffffu, m00t, 1));
        m00t = fmaxf(m00t, __shfl_xor_sync(0xffffffffu, m00t, 2));
        m01t = fmaxf(m01t, __shfl_xor_sync(0xffffffffu, m01t, 1));
        m01t = fmaxf(m01t, __shfl_xor_sync(0xffffffffu, m01t, 2));

        #pragma unroll
        for (int ks = 2; ks < 4; ++ks) {
            const uint32_t qx = ((2u * ks + l16) ^ l7) * 16;
            const uint32_t kx = ((2u * ks + l8) ^ l7) * 16;
            uint32_t ql1[4];
            ldsm4(ql1, smb + QL_OFF + qlrow + 2048 + qx);
            #pragma unroll
            for (int jp = 0; jp < 4; ++jp) {
                uint32_t kh4[4], kl4[4];
                ldsm4(kh4, sbase + KH_OFF + krowb + (uint32_t)jp * 2048 + kx);
                ldsm4(kl4, sbase + KL_OFF + krowb + (uint32_t)jp * 2048 + kx);
                mma16816h(s1[2 * jp],     qhr[1][ks], kh4[0], kh4[1]);
                mma16816h(s1[2 * jp + 1], qhr[1][ks], kh4[2], kh4[3]);
                mma16816h(s1[2 * jp],     ql1, kh4[0], kh4[1]);
                mma16816h(s1[2 * jp + 1], ql1, kh4[2], kh4[3]);
                mma16816h(s1[2 * jp],     qhr[1][ks], kl4[0], kl4[1]);
                mma16816h(s1[2 * jp + 1], qhr[1][ks], kl4[2], kl4[3]);
            }
        }

        // mb0: rescale + exp
        const float m00n = fmaxf(m[0][0], m00t);
        const float m01n = fmaxf(m[0][1], m01t);
        const float a00 = ex2f(m[0][0] - m00n);
        const float a01 = ex2f(m[0][1] - m01n);
        m[0][0] = m00n; m[0][1] = m01n;
        if (__any_sync(0xffffffffu, (a00 < 1.f) || (a01 < 1.f))) {
            #pragma unroll
            for (int nb = 0; nb < 8; ++nb) {
                o[0][nb][0] *= a00; o[0][nb][1] *= a00;
                o[0][nb][2] *= a01; o[0][nb][3] *= a01;
            }
            ls[0][0] *= a00; ls[0][1] *= a01;
        }
        uint32_t ph0[8][2];
        #pragma unroll
        for (int nb = 0; nb < 8; ++nb) {
            ph0[nb][0] = exp2pairh(s0[nb][0] - m00n, s0[nb][1] - m00n);
            ph0[nb][1] = exp2pairh(s0[nb][2] - m01n, s0[nb][3] - m01n);
        }

        // ======== phase 3: mb1 max/shfl first, O(mb0) fills latency ========
        float m10t = s1[0][0], m11t = s1[0][2];
        #pragma unroll
        for (int nb = 0; nb < 8; ++nb) {
            m10t = fmaxf(m10t, fmaxf(s1[nb][0], s1[nb][1]));
            m11t = fmaxf(m11t, fmaxf(s1[nb][2], s1[nb][3]));
        }
        m10t = fmaxf(m10t, __shfl_xor_sync(0xffffffffu, m10t, 1));
        m10t = fmaxf(m10t, __shfl_xor_sync(0xffffffffu, m10t, 2));
        m11t = fmaxf(m11t, __shfl_xor_sync(0xffffffffu, m11t, 1));
        m11t = fmaxf(m11t, __shfl_xor_sync(0xffffffffu, m11t, 2));

        {
            float2 r0 = hsum8(&ph0[0][0], 2);
            float2 r1 = hsum8(&ph0[0][1], 2);
            ls[0][0] += r0.x + r0.y;
            ls[0][1] += r1.x + r1.y;
        }

        #pragma unroll
        for (int kb = 0; kb < 4; ++kb) {
            uint32_t ah[4] = { ph0[2 * kb][0], ph0[2 * kb][1],
                               ph0[2 * kb + 1][0], ph0[2 * kb + 1][1] };
            const uint32_t vb_row = vrowb + (uint32_t)kb * 2048;
            #pragma unroll
            for (int np = 0; np < 4; ++np) {
                uint32_t vb[4];
                ldsm4t(vb, sbase + VH_OFF + vb_row + (((2u * np + l16) ^ l7) * 16));
                mma16816h(o[0][2 * np],     ah, vb[0], vb[1]);
                mma16816h(o[0][2 * np + 1], ah, vb[2], vb[3]);
            }
        }

        // mb1: rescale + exp
        const float m10n = fmaxf(m[1][0], m10t);
        const float m11n = fmaxf(m[1][1], m11t);
        const float a10 = ex2f(m[1][0] - m10n);
        const float a11 = ex2f(m[1][1] - m11n);
        m[1][0] = m10n; m[1][1] = m11n;
        if (__any_sync(0xffffffffu, (a10 < 1.f) || (a11 < 1.f))) {
            #pragma unroll
            for (int nb = 0; nb < 8; ++nb) {
                o[1][nb][0] *= a10; o[1][nb][1] *= a10;
                o[1][nb][2] *= a11; o[1][nb][3] *= a11;
            }
            ls[1][0] *= a10; ls[1][1] *= a11;
        }
        uint32_t ph1[8][2];
        #pragma unroll
        for (int nb = 0; nb < 8; ++nb) {
            ph1[nb][0] = exp2pairh(s1[nb][0] - m10n, s1[nb][1] - m10n);
            ph1[nb][1] = exp2pairh(s1[nb][2] - m11n, s1[nb][3] - m11n);
        }
        {
            float2 r0 = hsum8(&ph1[0][0], 2);
            float2 r1 = hsum8(&ph1[0][1], 2);
            ls[1][0] += r0.x + r0.y;
            ls[1][1] += r1.x + r1.y;
        }

        // ======== phase 4: O(mb1) ========
        #pragma unroll
        for (int kb = 0; kb < 4; ++kb) {
            uint32_t ah[4] = { ph1[2 * kb][0], ph1[2 * kb][1],
                               ph1[2 * kb + 1][0], ph1[2 * kb + 1][1] };
            const uint32_t vb_row = vrowb + (uint32_t)kb * 2048;
            #pragma unroll
            for (int np = 0; np < 4; ++np) {
                uint32_t vb[4];
                ldsm4t(vb, sbase + VH_OFF + vb_row + (((2u * np + l16) ^ l7) * 16));
                mma16816h(o[1][2 * np],     ah, vb[0], vb[1]);
                mma16816h(o[1][2 * np + 1], ah, vb[2], vb[3]);
            }
        }
    }

    // ---- epilogue: write un-normalized partials + (m, l) ----
    const int cg = ((b * NQB + qblk) * NCHUNK + chunk);
    float* obase = gOP + (size_t)cg * TQ * D_;

    #pragma unroll
    for (int mb = 0; mb < 2; ++mb) {
        #pragma unroll
        for (int h = 0; h < 2; ++h) {
            ls[mb][h] += __shfl_xor_sync(0xffffffffu, ls[mb][h], 1);
            ls[mb][h] += __shfl_xor_sync(0xffffffffu, ls[mb][h], 2);
        }
        const int row = wid * 32 + mb * 16 + (lane >> 2);
        float* op0 = obase + (size_t)row * D_ + 2 * (lane & 3);
        float* op1 = op0 + 8 * D_;
        #pragma unroll
        for (int nb = 0; nb < 8; ++nb) {
            *(float2*)(op0 + 8 * nb) = make_float2(o[mb][nb][0], o[mb][nb][1]);
            *(float2*)(op1 + 8 * nb) = make_float2(o[mb][nb][2], o[mb][nb][3]);
        }
        if ((lane & 3) == 0) {
            gML[(size_t)cg * TQ + row]     = make_float2(m[mb][0], ls[mb][0]);
            gML[(size_t)cg * TQ + row + 8] = make_float2(m[mb][1], ls[mb][1]);
        }
    }
}

// ===================== kernel C: combine partials ======================
__global__ __launch_bounds__(128)
void combine_kernel(float* __restrict__ O)
{
    const int item = blockIdx.x;          // 0..255
    const int row  = threadIdx.x;         // 0..127
    const int b    = item / NQB;
    const int qblk = item % NQB;

    float mv[NCHUNK], lv[NCHUNK];
    float M = -1e30f;
    #pragma unroll
    for (int q = 0; q < NCHUNK; ++q) {
        float2 p = gML[(size_t)(item * NCHUNK + q) * TQ + row];
        mv[q] = p.x; lv[q] = p.y;
        M = fmaxf(M, mv[q]);
    }
    float w[NCHUNK], L = 0.f;
    #pragma unroll
    for (int q = 0; q < NCHUNK; ++q) {
        w[q] = ex2f(mv[q] - M);
        L += w[q] * lv[q];
    }
    const float inv = 1.f / L;
    #pragma unroll
    for (int q = 0; q < NCHUNK; ++q) w[q] *= inv;

    float4* dst = (float4*)(O + ((size_t)b * SQ_ + qblk * TQ + row) * D_);
    #pragma unroll
    for (int c = 0; c < D_ / 4; ++c) {
        float4 r = make_float4(0.f, 0.f, 0.f, 0.f);
        #pragma unroll
        for (int q = 0; q < NCHUNK; ++q) {
            const float4 a = *(const float4*)(gOP
                + (size_t)(item * NCHUNK + q) * TQ * D_ + (size_t)row * D_ + 4 * c);
            r.x += w[q] * a.x;
            r.y += w[q] * a.y;
            r.z += w[q] * a.z;
            r.w += w[q] * a.w;
        }
        dst[c] = r;
    }
}

extern "C" void kernel_launch(void* const* d_in, const int* in_sizes, int n_in,
                              void* d_out, int out_size)
{
    (void)in_sizes; (void)n_in; (void)out_size;
    const float* q = (const float*)d_in[0];
    const float* k = (const float*)d_in[1];
    const float* v = (const float*)d_in[2];
    float* o = (float*)d_out;

    dim3 sgrid(NT, B_);
    split_kv_kernel<<<sgrid, 256>>>(k, v);

    dim3 qgrid(NQB, B_);
    split_q_kernel<<<qgrid, 128>>>(q);

    cudaFuncSetAttribute(attn_part_kernel,
                         cudaFuncAttributeMaxDynamicSharedMemorySize, SMEM_BYTES);
    dim3 agrid(NQB, B_, NCHUNK);
    attn_part_kernel<<<agrid, 128, SMEM_BYTES>>>();

    combine_kernel<<<NITEM, TQ>>>(o);
}

// round 15
// speedup vs baseline: 1.0549x; 1.0549x over previous
#include <cuda_runtime.h>
#include <cuda_fp16.h>
#include <cstdint>
#include <math.h>

// RingAttention out = softmax(Q K^T) V, B=32, SQ=1024, SKV=8192, D=64, fp32.
// R15: R14 + fp16 O-partials + properly parallel combine (1024x256).

#define B_   32
#define SQ_  1024
#define SKV_ 8192
#define D_   64
#define TQ   128
#define TKV  64
#define NT   (SKV_ / TKV)      // 128
#define NCHUNK 8
#define CT   (NT / NCHUNK)     // 16
#define NQB  (SQ_ / TQ)        // 8
#define NITEM (B_ * NQB)       // 256

#define BLK_BYTES 24576
__device__ uint8_t gKV[(size_t)B_ * NT * BLK_BYTES];            // 96 MB
__device__ uint8_t gQ[(size_t)NITEM * 32768];                   // 8 MB
__device__ __half  gOP[(size_t)NITEM * NCHUNK * TQ * D_];       // 33.5 MB fp16 partials
__device__ float2  gML[(size_t)NITEM * NCHUNK * TQ];            // 2 MB (m, l)

#define QL_OFF 0
#define STG0   16384
#define KH_OFF 0
#define KL_OFF 8192
#define VH_OFF 16384
#define SMEM_BYTES (16384 + 2 * BLK_BYTES)   // 65536

__device__ __forceinline__ uint32_t smem_u32(const void* p) {
    uint32_t a;
    asm("{ .reg .u64 t; cvta.to.shared.u64 t, %1; cvt.u32.u64 %0, t; }" : "=r"(a) : "l"(p));
    return a;
}
__device__ __forceinline__ void ldsm4(uint32_t r[4], uint32_t a) {
    asm volatile("ldmatrix.sync.aligned.m8n8.x4.shared.b16 {%0,%1,%2,%3}, [%4];"
                 : "=r"(r[0]), "=r"(r[1]), "=r"(r[2]), "=r"(r[3]) : "r"(a));
}
__device__ __forceinline__ void ldsm4t(uint32_t r[4], uint32_t a) {
    asm volatile("ldmatrix.sync.aligned.m8n8.x4.trans.shared.b16 {%0,%1,%2,%3}, [%4];"
                 : "=r"(r[0]), "=r"(r[1]), "=r"(r[2]), "=r"(r[3]) : "r"(a));
}
__device__ __forceinline__ void mma16816h(float* c, const uint32_t* a, uint32_t b0, uint32_t b1) {
    asm volatile("mma.sync.aligned.m16n8k16.row.col.f32.f16.f16.f32 "
                 "{%0,%1,%2,%3}, {%4,%5,%6,%7}, {%8,%9}, {%0,%1,%2,%3};"
                 : "+f"(c[0]), "+f"(c[1]), "+f"(c[2]), "+f"(c[3])
                 : "r"(a[0]), "r"(a[1]), "r"(a[2]), "r"(a[3]), "r"(b0), "r"(b1));
}
__device__ __forceinline__ float ex2f(float x) {
    float r;
    asm("ex2.approx.f32 %0, %1;" : "=f"(r) : "f"(x));
    return r;
}
__device__ __forceinline__ uint32_t exp2pairh(float x, float y) {
    uint32_t d, r;
    asm("cvt.rn.f16x2.f32 %0, %1, %2;" : "=r"(d) : "f"(y), "f"(x));
    asm("ex2.approx.f16x2 %0, %1;" : "=r"(r) : "r"(d));
    return r;
}
__device__ __forceinline__ uint32_t packh(float x, float y) {
    __half2 h = __floats2half2_rn(x, y);
    return *reinterpret_cast<uint32_t*>(&h);
}
__device__ __forceinline__ void split2h(float x, float y, uint32_t& h, uint32_t& l) {
    __half2 hp = __floats2half2_rn(x, y);
    float rx = x - __half2float(__low2half(hp));
    float ry = y - __half2float(__high2half(hp));
    __half2 lp = __floats2half2_rn(rx, ry);
    h = *reinterpret_cast<uint32_t*>(&hp);
    l = *reinterpret_cast<uint32_t*>(&lp);
}
__device__ __forceinline__ void cvt8h(float4 a, float4 b, uint4& h, uint4& l) {
    split2h(a.x, a.y, h.x, l.x);
    split2h(a.z, a.w, h.y, l.y);
    split2h(b.x, b.y, h.z, l.z);
    split2h(b.z, b.w, h.w, l.w);
}
__device__ __forceinline__ uint4 cvt8h1(float4 a, float4 b) {
    uint4 h;
    h.x = packh(a.x, a.y);
    h.y = packh(a.z, a.w);
    h.z = packh(b.x, b.y);
    h.w = packh(b.z, b.w);
    return h;
}
__device__ __forceinline__ float2 hsum8(const uint32_t* p, int stride) {
    __half2 a0 = __hadd2(*(const __half2*)&p[0 * stride], *(const __half2*)&p[1 * stride]);
    __half2 a1 = __hadd2(*(const __half2*)&p[2 * stride], *(const __half2*)&p[3 * stride]);
    __half2 a2 = __hadd2(*(const __half2*)&p[4 * stride], *(const __half2*)&p[5 * stride]);
    __half2 a3 = __hadd2(*(const __half2*)&p[6 * stride], *(const __half2*)&p[7 * stride]);
    __half2 s = __hadd2(__hadd2(a0, a1), __hadd2(a2, a3));
    return __half22float2(s);
}
#define CP_ASYNC16(dst, src) \
    asm volatile("cp.async.cg.shared.global [%0], [%1], 16;" :: "r"(dst), "l"(src))
#define CP_COMMIT() asm volatile("cp.async.commit_group;" ::: "memory")
#define CP_WAIT0()  asm volatile("cp.async.wait_group 0;" ::: "memory")

// ===================== kernel A1: split K/V ======================
__global__ __launch_bounds__(256)
void split_kv_kernel(const float* __restrict__ K, const float* __restrict__ V)
{
    const int t = blockIdx.x;
    const int b = blockIdx.y;
    const int tid = threadIdx.x;

    const float* Kt = K + ((size_t)b * SKV_ + (size_t)t * TKV) * D_;
    const float* Vt = V + ((size_t)b * SKV_ + (size_t)t * TKV) * D_;
    uint8_t* blk = gKV + ((size_t)b * NT + t) * BLK_BYTES;

    #pragma unroll
    for (int uu = 0; uu < 2; ++uu) {
        const int u = tid + 256 * uu;
        const int r = u >> 3;
        const int c = u & 7;
        const uint32_t off = (uint32_t)r * 128 + (uint32_t)((c ^ (r & 7)) * 16);
        const float4* kp = (const float4*)(Kt + (size_t)r * D_ + c * 8);
        const float4* vp = (const float4*)(Vt + (size_t)r * D_ + c * 8);
        uint4 h, l;
        cvt8h(kp[0], kp[1], h, l);
        *(uint4*)(blk + KH_OFF + off) = h;
        *(uint4*)(blk + KL_OFF + off) = l;
        *(uint4*)(blk + VH_OFF + off) = cvt8h1(vp[0], vp[1]);
    }
}

// ===================== kernel A2: split Q (pre-scaled by log2 e) ======================
__global__ __launch_bounds__(128)
void split_q_kernel(const float* __restrict__ Q)
{
    const int qblk = blockIdx.x;
    const int b    = blockIdx.y;
    const int r    = threadIdx.x;

    const float4* qp = (const float4*)(Q + ((size_t)b * SQ_ + qblk * TQ + r) * D_);
    uint8_t* dst = gQ + (size_t)(b * NQB + qblk) * 32768;
    const float LG2E = 1.4426950408889634f;

    #pragma unroll
    for (int c = 0; c < 8; ++c) {
        float4 f0 = qp[2 * c], f1 = qp[2 * c + 1];
        f0.x *= LG2E; f0.y *= LG2E; f0.z *= LG2E; f0.w *= LG2E;
        f1.x *= LG2E; f1.y *= LG2E; f1.z *= LG2E; f1.w *= LG2E;
        uint4 h, l;
        cvt8h(f0, f1, h, l);
        uint32_t x = (uint32_t)r * 128 + (uint32_t)((c ^ (r & 7)) * 16);
        *(uint4*)(dst + x)         = h;
        *(uint4*)(dst + 16384 + x) = l;
    }
}

// ===================== kernel B: attention partial ======================
__global__ __launch_bounds__(128, 2)
void attn_part_kernel()
{
    extern __shared__ char sm[];
    const uint32_t smb = smem_u32(sm);
    const int tid  = threadIdx.x;
    const int wid  = tid >> 5;
    const int lane = tid & 31;
    const uint32_t l7  = lane & 7;
    const uint32_t l8  = (lane >> 3) & 1;
    const uint32_t l15 = lane & 15;
    const uint32_t l16 = (uint32_t)lane >> 4;
    const int qblk  = blockIdx.x;
    const int b     = blockIdx.y;
    const int chunk = blockIdx.z;
    const int t0 = chunk * CT;

    const uint8_t* blk0 = gKV + (size_t)b * NT * BLK_BYTES;
    const uint8_t* qsrc = gQ + (size_t)(b * NQB + qblk) * 32768;

    // ---- prologue: cp.async Q images (QH -> stage0 transient, QL resident) ----
    {
        const uint32_t dstH = smb + STG0 + (uint32_t)tid * 16;
        const uint32_t dstL = smb + QL_OFF + (uint32_t)tid * 16;
        #pragma unroll
        for (int i = 0; i < 8; ++i) {
            CP_ASYNC16(dstH + i * 2048, qsrc + (size_t)tid * 16 + i * 2048);
            CP_ASYNC16(dstL + i * 2048, qsrc + 16384 + (size_t)tid * 16 + i * 2048);
        }
        CP_COMMIT();
        CP_WAIT0();
    }
    __syncthreads();

    uint32_t qhr[2][4][4];
    #pragma unroll
    for (int mb = 0; mb < 2; ++mb)
        #pragma unroll
        for (int ks = 0; ks < 4; ++ks) {
            uint32_t a = smb + STG0
                       + (uint32_t)(wid * 32 + mb * 16 + (int)l15) * 128
                       + (((2u * ks + l16) ^ l7) * 16);
            ldsm4(qhr[mb][ks], a);
        }
    __syncthreads();

    {
        const uint32_t dst = smb + STG0 + (uint32_t)tid * 16;
        const uint8_t* src = blk0 + (size_t)t0 * BLK_BYTES + (size_t)tid * 16;
        #pragma unroll
        for (int i = 0; i < 12; ++i)
            CP_ASYNC16(dst + i * 2048, src + i * 2048);
        CP_COMMIT();
    }

    const uint32_t krowb = (8 * l16 + l7) * 128;
    const uint32_t vrowb = l15 * 128;
    const uint32_t qlrow = (uint32_t)(wid * 32 + (int)l15) * 128;

    float o[2][8][4];
    float ls[2][2];
    #pragma unroll
    for (int mb = 0; mb < 2; ++mb) {
        #pragma unroll
        for (int nb = 0; nb < 8; ++nb)
            #pragma unroll
            for (int c = 0; c < 4; ++c) o[mb][nb][c] = 0.f;
        ls[mb][0] = 0.f; ls[mb][1] = 0.f;
    }
    float m[2][2] = {{-1e30f, -1e30f}, {-1e30f, -1e30f}};

    for (int lt = 0; lt < CT; ++lt) {
        const int t = t0 + lt;
        CP_WAIT0();
        __syncthreads();

        if (lt + 1 < CT) {
            const uint32_t dst = smb + STG0 + (uint32_t)(((lt + 1) & 1) * BLK_BYTES)
                                 + (uint32_t)tid * 16;
            const uint8_t* src = blk0 + (size_t)(t + 1) * BLK_BYTES + (size_t)tid * 16;
            #pragma unroll
            for (int i = 0; i < 12; ++i)
                CP_ASYNC16(dst + i * 2048, src + i * 2048);
            CP_COMMIT();
        }

        const uint32_t sbase = smb + STG0 + (uint32_t)((lt & 1) * BLK_BYTES);

        // ======== phase 1: S(mb0) full + S(mb1) ks0-1 ========
        float s0[8][4], s1[8][4];
        #pragma unroll
        for (int nb = 0; nb < 8; ++nb)
            #pragma unroll
            for (int c = 0; c < 4; ++c) { s0[nb][c] = 0.f; s1[nb][c] = 0.f; }

        #pragma unroll
        for (int ks = 0; ks < 4; ++ks) {
            const uint32_t qx = ((2u * ks + l16) ^ l7) * 16;
            const uint32_t kx = ((2u * ks + l8) ^ l7) * 16;
            uint32_t ql0[4], ql1[4];
            ldsm4(ql0, smb + QL_OFF + qlrow + qx);
            if (ks < 2) ldsm4(ql1, smb + QL_OFF + qlrow + 2048 + qx);
            #pragma unroll
            for (int jp = 0; jp < 4; ++jp) {
                uint32_t kh4[4], kl4[4];
                ldsm4(kh4, sbase + KH_OFF + krowb + (uint32_t)jp * 2048 + kx);
                ldsm4(kl4, sbase + KL_OFF + krowb + (uint32_t)jp * 2048 + kx);
                mma16816h(s0[2 * jp],     qhr[0][ks], kh4[0], kh4[1]);
                mma16816h(s0[2 * jp + 1], qhr[0][ks], kh4[2], kh4[3]);
                mma16816h(s0[2 * jp],     ql0, kh4[0], kh4[1]);
                mma16816h(s0[2 * jp + 1], ql0, kh4[2], kh4[3]);
                mma16816h(s0[2 * jp],     qhr[0][ks], kl4[0], kl4[1]);
                mma16816h(s0[2 * jp + 1], qhr[0][ks], kl4[2], kl4[3]);
                if (ks < 2) {
                    mma16816h(s1[2 * jp],     qhr[1][ks], kh4[0], kh4[1]);
                    mma16816h(s1[2 * jp + 1], qhr[1][ks], kh4[2], kh4[3]);
                    mma16816h(s1[2 * jp],     ql1, kh4[0], kh4[1]);
                    mma16816h(s1[2 * jp + 1], ql1, kh4[2], kh4[3]);
                    mma16816h(s1[2 * jp],     qhr[1][ks], kl4[0], kl4[1]);
                    mma16816h(s1[2 * jp + 1], qhr[1][ks], kl4[2], kl4[3]);
                }
            }
        }

        // ======== phase 2: mb0 max/shfl first, S(mb1) ks2-3 fills latency ========
        float m00t = s0[0][0], m01t = s0[0][2];
        #pragma unroll
        for (int nb = 0; nb < 8; ++nb) {
            m00t = fmaxf(m00t, fmaxf(s0[nb][0], s0[nb][1]));
            m01t = fmaxf(m01t, fmaxf(s0[nb][2], s0[nb][3]));
        }
        m00t = fmaxf(m00t, __shfl_xor_sync(0xffffffffu, m00t, 1));
        m00t = fmaxf(m00t, __shfl_xor_sync(0xffffffffu, m00t, 2));
        m01t = fmaxf(m01t, __shfl_xor_sync(0xffffffffu, m01t, 1));
        m01t = fmaxf(m01t, __shfl_xor_sync(0xffffffffu, m01t, 2));

        #pragma unroll
        for (int ks = 2; ks < 4; ++ks) {
            const uint32_t qx = ((2u * ks + l16) ^ l7) * 16;
            const uint32_t kx = ((2u * ks + l8) ^ l7) * 16;
            uint32_t ql1[4];
            ldsm4(ql1, smb + QL_OFF + qlrow + 2048 + qx);
            #pragma unroll
            for (int jp = 0; jp < 4; ++jp) {
                uint32_t kh4[4], kl4[4];
                ldsm4(kh4, sbase + KH_OFF + krowb + (uint32_t)jp * 2048 + kx);
                ldsm4(kl4, sbase + KL_OFF + krowb + (uint32_t)jp * 2048 + kx);
                mma16816h(s1[2 * jp],     qhr[1][ks], kh4[0], kh4[1]);
                mma16816h(s1[2 * jp + 1], qhr[1][ks], kh4[2], kh4[3]);
                mma16816h(s1[2 * jp],     ql1, kh4[0], kh4[1]);
                mma16816h(s1[2 * jp + 1], ql1, kh4[2], kh4[3]);
                mma16816h(s1[2 * jp],     qhr[1][ks], kl4[0], kl4[1]);
                mma16816h(s1[2 * jp + 1], qhr[1][ks], kl4[2], kl4[3]);
            }
        }

        // mb0: rescale + exp
        const float m00n = fmaxf(m[0][0], m00t);
        const float m01n = fmaxf(m[0][1], m01t);
        const float a00 = ex2f(m[0][0] - m00n);
        const float a01 = ex2f(m[0][1] - m01n);
        m[0][0] = m00n; m[0][1] = m01n;
        if (__any_sync(0xffffffffu, (a00 < 1.f) || (a01 < 1.f))) {
            #pragma unroll
            for (int nb = 0; nb < 8; ++nb) {
                o[0][nb][0] *= a00; o[0][nb][1] *= a00;
                o[0][nb][2] *= a01; o[0][nb][3] *= a01;
            }
            ls[0][0] *= a00; ls[0][1] *= a01;
        }
        uint32_t ph0[8][2];
        #pragma unroll
        for (int nb = 0; nb < 8; ++nb) {
            ph0[nb][0] = exp2pairh(s0[nb][0] - m00n, s0[nb][1] - m00n);
            ph0[nb][1] = exp2pairh(s0[nb][2] - m01n, s0[nb][3] - m01n);
        }

        // ======== phase 3: mb1 max/shfl first, O(mb0) fills latency ========
        float m10t = s1[0][0], m11t = s1[0][2];
        #pragma unroll
        for (int nb = 0; nb < 8; ++nb) {
            m10t = fmaxf(m10t, fmaxf(s1[nb][0], s1[nb][1]));
            m11t = fmaxf(m11t, fmaxf(s1[nb][2], s1[nb][3]));
        }
        m10t = fmaxf(m10t, __shfl_xor_sync(0xffffffffu, m10t, 1));
        m10t = fmaxf(m10t, __shfl_xor_sync(0xffffffffu, m10t, 2));
        m11t = fmaxf(m11t, __shfl_xor_sync(0xffffffffu, m11t, 1));
        m11t = fmaxf(m11t, __shfl_xor_sync(0xffffffffu, m11t, 2));

        {
            float2 r0 = hsum8(&ph0[0][0], 2);
            float2 r1 = hsum8(&ph0[0][1], 2);
            ls[0][0] += r0.x + r0.y;
            ls[0][1] += r1.x + r1.y;
        }

        #pragma unroll
        for (int kb = 0; kb < 4; ++kb) {
            uint32_t ah[4] = { ph0[2 * kb][0], ph0[2 * kb][1],
                               ph0[2 * kb + 1][0], ph0[2 * kb + 1][1] };
            const uint32_t vb_row = vrowb + (uint32_t)kb * 2048;
            #pragma unroll
            for (int np = 0; np < 4; ++np) {
                uint32_t vb[4];
                ldsm4t(vb, sbase + VH_OFF + vb_row + (((2u * np + l16) ^ l7) * 16));
                mma16816h(o[0][2 * np],     ah, vb[0], vb[1]);
                mma16816h(o[0][2 * np + 1], ah, vb[2], vb[3]);
            }
        }

        // mb1: rescale + exp
        const float m10n = fmaxf(m[1][0], m10t);
        const float m11n = fmaxf(m[1][1], m11t);
        const float a10 = ex2f(m[1][0] - m10n);
        const float a11 = ex2f(m[1][1] - m11n);
        m[1][0] = m10n; m[1][1] = m11n;
        if (__any_sync(0xffffffffu, (a10 < 1.f) || (a11 < 1.f))) {
            #pragma unroll
            for (int nb = 0; nb < 8; ++nb) {
                o[1][nb][0] *= a10; o[1][nb][1] *= a10;
                o[1][nb][2] *= a11; o[1][nb][3] *= a11;
            }
            ls[1][0] *= a10; ls[1][1] *= a11;
        }
        uint32_t ph1[8][2];
        #pragma unroll
        for (int nb = 0; nb < 8; ++nb) {
            ph1[nb][0] = exp2pairh(s1[nb][0] - m10n, s1[nb][1] - m10n);
            ph1[nb][1] = exp2pairh(s1[nb][2] - m11n, s1[nb][3] - m11n);
        }
        {
            float2 r0 = hsum8(&ph1[0][0], 2);
            float2 r1 = hsum8(&ph1[0][1], 2);
            ls[1][0] += r0.x + r0.y;
            ls[1][1] += r1.x + r1.y;
        }

        // ======== phase 4: O(mb1) ========
        #pragma unroll
        for (int kb = 0; kb < 4; ++kb) {
            uint32_t ah[4] = { ph1[2 * kb][0], ph1[2 * kb][1],
                               ph1[2 * kb + 1][0], ph1[2 * kb + 1][1] };
            const uint32_t vb_row = vrowb + (uint32_t)kb * 2048;
            #pragma unroll
            for (int np = 0; np < 4; ++np) {
                uint32_t vb[4];
                ldsm4t(vb, sbase + VH_OFF + vb_row + (((2u * np + l16) ^ l7) * 16));
                mma16816h(o[1][2 * np],     ah, vb[0], vb[1]);
                mma16816h(o[1][2 * np + 1], ah, vb[2], vb[3]);
            }
        }
    }

    // ---- epilogue: write fp16 un-normalized partials + (m, l) ----
    const int cg = ((b * NQB + qblk) * NCHUNK + chunk);
    __half* obase = gOP + (size_t)cg * TQ * D_;

    #pragma unroll
    for (int mb = 0; mb < 2; ++mb) {
        #pragma unroll
        for (int h = 0; h < 2; ++h) {
            ls[mb][h] += __shfl_xor_sync(0xffffffffu, ls[mb][h], 1);
            ls[mb][h] += __shfl_xor_sync(0xffffffffu, ls[mb][h], 2);
        }
        const int row = wid * 32 + mb * 16 + (lane >> 2);
        __half* op0 = obase + (size_t)row * D_ + 2 * (lane & 3);
        __half* op1 = op0 + 8 * D_;
        #pragma unroll
        for (int nb = 0; nb < 8; ++nb) {
            *(uint32_t*)(op0 + 8 * nb) = packh(o[mb][nb][0], o[mb][nb][1]);
            *(uint32_t*)(op1 + 8 * nb) = packh(o[mb][nb][2], o[mb][nb][3]);
        }
        if ((lane & 3) == 0) {
            gML[(size_t)cg * TQ + row]     = make_float2(m[mb][0], ls[mb][0]);
            gML[(size_t)cg * TQ + row + 8] = make_float2(m[mb][1], ls[mb][1]);
        }
    }
}

// ===================== kernel C: combine partials ======================
// 262144 threads: thread = (global row, 1/8 of D). 1024 blocks x 256.
__global__ __launch_bounds__(256)
void combine_kernel(float* __restrict__ O)
{
    const int gid = blockIdx.x * 256 + threadIdx.x;   // 0..262143
    const int rowg = gid >> 3;                        // 0..32767
    const int part = gid & 7;                         // 8 floats of D
    const int item = rowg >> 7;
    const int row  = rowg & 127;
    const int b    = item / NQB;
    const int qblk = item % NQB;

    float mv[NCHUNK], lv[NCHUNK];
    float M = -1e30f;
    #pragma unroll
    for (int q = 0; q < NCHUNK; ++q) {
        float2 p = gML[(size_t)(item * NCHUNK + q) * TQ + row];
        mv[q] = p.x; lv[q] = p.y;
        M = fmaxf(M, mv[q]);
    }
    float w[NCHUNK], L = 0.f;
    #pragma unroll
    for (int q = 0; q < NCHUNK; ++q) {
        w[q] = ex2f(mv[q] - M);
        L += w[q] * lv[q];
    }
    const float inv = 1.f / L;

    float acc[8];
    #pragma unroll
    for (int i = 0; i < 8; ++i) acc[i] = 0.f;

    #pragma unroll
    for (int q = 0; q < NCHUNK; ++q) {
        const __half* src = gOP + (size_t)(item * NCHUNK + q) * TQ * D_
                          + (size_t)row * D_ + part * 8;
        uint4 raw = *(const uint4*)src;   // 8 halves
        const uint32_t* rw = (const uint32_t*)&raw;
        const float wq = w[q] * inv;
        #pragma unroll
        for (int j = 0; j < 4; ++j) {
            float2 f = __half22float2(*(const __half2*)&rw[j]);
            acc[2 * j]     += wq * f.x;
            acc[2 * j + 1] += wq * f.y;
        }
    }

    float4* dst = (float4*)(O + ((size_t)b * SQ_ + qblk * TQ + row) * D_ + part * 8);
    dst[0] = make_float4(acc[0], acc[1], acc[2], acc[3]);
    dst[1] = make_float4(acc[4], acc[5], acc[6], acc[7]);
}

extern "C" void kernel_launch(void* const* d_in, const int* in_sizes, int n_in,
                              void* d_out, int out_size)
{
    (void)in_sizes; (void)n_in; (void)out_size;
    const float* q = (const float*)d_in[0];
    const float* k = (const float*)d_in[1];
    const float* v = (const float*)d_in[2];
    float* o = (float*)d_out;

    dim3 sgrid(NT, B_);
    split_kv_kernel<<<sgrid, 256>>>(k, v);

    dim3 qgrid(NQB, B_);
    split_q_kernel<<<qgrid, 128>>>(q);

    cudaFuncSetAttribute(attn_part_kernel,
                         cudaFuncAttributeMaxDynamicSharedMemorySize, SMEM_BYTES);
    dim3 agrid(NQB, B_, NCHUNK);
    attn_part_kernel<<<agrid, 128, SMEM_BYTES>>>();

    combine_kernel<<<(NITEM * NCHUNK * TQ) / 256 /* =1024 */, 256>>>(o);
}